// round 2
// baseline (speedup 1.0000x reference)
#include <cuda_runtime.h>
#include <math.h>

// Problem constants
#define BB   4
#define DIMC 256
#define HH   64
#define WW   64
#define HWSZ 4096          // H*W
#define NHD  8             // num heads
#define HDC  32            // head dim
#define NPP  8             // points
#define TQ   32            // tokens per block

// Scratch: v_proj in [b][h][yx][d] layout (d contiguous, 128B per pixel-head)
__device__ float g_vp[BB * NHD * HWSZ * HDC];   // 16.7 MB

// ---------------------------------------------------------------------------
// Kernel 1: v_proj = value(NCHW gathered) @ W_val^T + b_val
// Block: 32 tokens, 256 threads. smem: vs[256][33] + outs[256][33]
// ---------------------------------------------------------------------------
__global__ void vproj_kernel(const float* __restrict__ value,
                             const float* __restrict__ Wval,
                             const float* __restrict__ bval) {
    extern __shared__ float sm[];
    float* vs   = sm;              // [256][33] input tile (k-major, padded)
    float* outs = sm + 256 * 33;   // [256][33] output tile (n-major, padded)

    const int blk = blockIdx.x;
    const int b   = (blk * TQ) >> 12;
    const int yx0 = (blk * TQ) & (HWSZ - 1);
    const int tid = threadIdx.x;

    // Load value tile: vs[k][t] = value[b, k, yx0+t]  (coalesced on t)
    for (int idx = tid; idx < DIMC * TQ; idx += 256) {
        const int k = idx >> 5, t = idx & 31;
        vs[k * 33 + t] = value[(b * DIMC + k) * HWSZ + yx0 + t];
    }
    __syncthreads();

    const int w = tid >> 5;   // warp id -> covers n in [w*32, w*32+32)
    const int t = tid & 31;   // lane -> token

    for (int j = 0; j < 32; j += 4) {
        const int n = w * 32 + j;
        float a0 = bval[n + 0], a1 = bval[n + 1], a2 = bval[n + 2], a3 = bval[n + 3];
        const float4* W0 = (const float4*)(Wval + (n + 0) * DIMC);
        const float4* W1 = (const float4*)(Wval + (n + 1) * DIMC);
        const float4* W2 = (const float4*)(Wval + (n + 2) * DIMC);
        const float4* W3 = (const float4*)(Wval + (n + 3) * DIMC);
        #pragma unroll 4
        for (int k4 = 0; k4 < DIMC / 4; k4++) {
            const float4 w0 = W0[k4], w1 = W1[k4], w2 = W2[k4], w3 = W3[k4];
            const int k = k4 * 4;
            const float q0 = vs[(k + 0) * 33 + t];
            const float q1 = vs[(k + 1) * 33 + t];
            const float q2 = vs[(k + 2) * 33 + t];
            const float q3 = vs[(k + 3) * 33 + t];
            a0 += q0 * w0.x + q1 * w0.y + q2 * w0.z + q3 * w0.w;
            a1 += q0 * w1.x + q1 * w1.y + q2 * w1.z + q3 * w1.w;
            a2 += q0 * w2.x + q1 * w2.y + q2 * w2.z + q3 * w2.w;
            a3 += q0 * w3.x + q1 * w3.y + q2 * w3.z + q3 * w3.w;
        }
        outs[(n + 0) * 33 + t] = a0;
        outs[(n + 1) * 33 + t] = a1;
        outs[(n + 2) * 33 + t] = a2;
        outs[(n + 3) * 33 + t] = a3;
    }
    __syncthreads();

    // Coalesced write to g_vp[b][h][yx0+t][d]
    for (int idx = tid; idx < NHD * TQ * HDC; idx += 256) {
        const int h  = idx >> 10;
        const int t2 = (idx >> 5) & 31;
        const int d  = idx & 31;
        g_vp[(((b * NHD + h) * HWSZ) + yx0 + t2) * HDC + d] = outs[(h * 32 + d) * 33 + t2];
    }
}

// ---------------------------------------------------------------------------
// Kernel 2: fused loc/att GEMM + softmax + bilinear sampling + out GEMM
// Block: 32 tokens, 256 threads.
// smem: qs[256][33] (aliased by outs) + locatt[192][32] + msda[256][33]
// ---------------------------------------------------------------------------
__global__ void fused_kernel(const float* __restrict__ query,
                             const float* __restrict__ Wloc,
                             const float* __restrict__ bloc,
                             const float* __restrict__ Watt,
                             const float* __restrict__ batt,
                             const float* __restrict__ Wout,
                             const float* __restrict__ bout,
                             float* __restrict__ out) {
    extern __shared__ float sm[];
    float* qs     = sm;                       // [256][33]
    float* locatt = sm + 256 * 33;            // [192][32]  (loc 0..127, att 128..191)
    float* msda   = sm + 256 * 33 + 192 * 32; // [256][33]
    float* outs   = sm;                       // alias qs (qs dead after GEMM1)

    const int blk = blockIdx.x;
    const int b   = (blk * TQ) >> 12;
    const int yx0 = (blk * TQ) & (HWSZ - 1);
    const int tid = threadIdx.x;
    const int w   = tid >> 5;
    const int t   = tid & 31;

    // ---- load q tile ----
    for (int idx = tid; idx < DIMC * TQ; idx += 256) {
        const int k = idx >> 5, tt = idx & 31;
        qs[k * 33 + tt] = query[(b * DIMC + k) * HWSZ + yx0 + tt];
    }
    __syncthreads();

    // ---- GEMM1: loc (128 rows) + att (64 rows). warp w covers n in [w*24, w*24+24) ----
    for (int g = 0; g < 6; g++) {
        const int n0 = w * 24 + g * 4;
        float acc[4];
        const float4* Wr[4];
        #pragma unroll
        for (int i = 0; i < 4; i++) {
            const int n = n0 + i;
            if (n < 128) { Wr[i] = (const float4*)(Wloc + n * DIMC);        acc[i] = bloc[n]; }
            else         { Wr[i] = (const float4*)(Watt + (n - 128) * DIMC); acc[i] = batt[n - 128]; }
        }
        #pragma unroll 4
        for (int k4 = 0; k4 < DIMC / 4; k4++) {
            const float4 w0 = Wr[0][k4], w1 = Wr[1][k4], w2 = Wr[2][k4], w3 = Wr[3][k4];
            const int k = k4 * 4;
            const float q0 = qs[(k + 0) * 33 + t];
            const float q1 = qs[(k + 1) * 33 + t];
            const float q2 = qs[(k + 2) * 33 + t];
            const float q3 = qs[(k + 3) * 33 + t];
            acc[0] += q0 * w0.x + q1 * w0.y + q2 * w0.z + q3 * w0.w;
            acc[1] += q0 * w1.x + q1 * w1.y + q2 * w1.z + q3 * w1.w;
            acc[2] += q0 * w2.x + q1 * w2.y + q2 * w2.z + q3 * w2.w;
            acc[3] += q0 * w3.x + q1 * w3.y + q2 * w3.z + q3 * w3.w;
        }
        #pragma unroll
        for (int i = 0; i < 4; i++) locatt[(n0 + i) * 32 + t] = acc[i];
    }
    __syncthreads();

    // ---- softmax over 8 points per (token, head). thread = (h = tid/32, t = tid%32) ----
    {
        const int h = tid >> 5;
        float e[NPP];
        float m = -1e30f;
        #pragma unroll
        for (int p = 0; p < NPP; p++) {
            e[p] = locatt[(128 + h * NPP + p) * 32 + t];
            m = fmaxf(m, e[p]);
        }
        float s = 0.f;
        #pragma unroll
        for (int p = 0; p < NPP; p++) { e[p] = expf(e[p] - m); s += e[p]; }
        const float inv = 1.f / s;
        #pragma unroll
        for (int p = 0; p < NPP; p++) locatt[(128 + h * NPP + p) * 32 + t] = e[p] * inv;
    }
    __syncthreads();

    // ---- sampling: warp handles (token,head) pairs; lane = channel d ----
    for (int pair = w; pair < TQ * NHD; pair += 8) {
        const int tt = pair >> 3;
        const int h  = pair & 7;
        const int d  = t;  // lane = channel
        const float* vpb = g_vp + ((b * NHD + h) * HWSZ) * HDC;
        float acc = 0.f;
        #pragma unroll
        for (int p = 0; p < NPP; p++) {
            const float lx = locatt[((h * NPP + p) * 2 + 0) * 32 + tt];
            const float ly = locatt[((h * NPP + p) * 2 + 1) * 32 + tt];
            const float aw = locatt[(128 + h * NPP + p) * 32 + tt];
            // grid_sample: x = ((2*loc-1)+1)*W/2 - 0.5 = loc*W - 0.5
            const float x = lx * (float)WW - 0.5f;
            const float y = ly * (float)HH - 0.5f;
            const float xf = floorf(x), yf = floorf(y);
            const float wx = x - xf, wy = y - yf;
            const int x0 = (int)xf, y0 = (int)yf;
            const int x1 = x0 + 1,  y1 = y0 + 1;
            const bool vx0 = (x0 >= 0) && (x0 < WW);
            const bool vx1 = (x1 >= 0) && (x1 < WW);
            const bool vy0 = (y0 >= 0) && (y0 < HH);
            const bool vy1 = (y1 >= 0) && (y1 < HH);
            const float v00 = (vx0 && vy0) ? vpb[(y0 * WW + x0) * HDC + d] : 0.f;
            const float v01 = (vx1 && vy0) ? vpb[(y0 * WW + x1) * HDC + d] : 0.f;
            const float v10 = (vx0 && vy1) ? vpb[(y1 * WW + x0) * HDC + d] : 0.f;
            const float v11 = (vx1 && vy1) ? vpb[(y1 * WW + x1) * HDC + d] : 0.f;
            const float top = v00 * (1.f - wx) + v01 * wx;
            const float bot = v10 * (1.f - wx) + v11 * wx;
            acc += aw * (top * (1.f - wy) + bot * wy);
        }
        msda[(h * HDC + d) * 33 + tt] = acc;
    }
    __syncthreads();

    // ---- GEMM2: out[t][n] = msda[t] . Wout[n] + bout[n]. warp w covers n in [w*32, w*32+32) ----
    for (int j = 0; j < 32; j += 4) {
        const int n = w * 32 + j;
        float a0 = bout[n + 0], a1 = bout[n + 1], a2 = bout[n + 2], a3 = bout[n + 3];
        const float4* W0 = (const float4*)(Wout + (n + 0) * DIMC);
        const float4* W1 = (const float4*)(Wout + (n + 1) * DIMC);
        const float4* W2 = (const float4*)(Wout + (n + 2) * DIMC);
        const float4* W3 = (const float4*)(Wout + (n + 3) * DIMC);
        #pragma unroll 4
        for (int k4 = 0; k4 < DIMC / 4; k4++) {
            const float4 w0 = W0[k4], w1 = W1[k4], w2 = W2[k4], w3 = W3[k4];
            const int k = k4 * 4;
            const float m0 = msda[(k + 0) * 33 + t];
            const float m1 = msda[(k + 1) * 33 + t];
            const float m2 = msda[(k + 2) * 33 + t];
            const float m3 = msda[(k + 3) * 33 + t];
            a0 += m0 * w0.x + m1 * w0.y + m2 * w0.z + m3 * w0.w;
            a1 += m0 * w1.x + m1 * w1.y + m2 * w1.z + m3 * w1.w;
            a2 += m0 * w2.x + m1 * w2.y + m2 * w2.z + m3 * w2.w;
            a3 += m0 * w3.x + m1 * w3.y + m2 * w3.z + m3 * w3.w;
        }
        outs[(n + 0) * 33 + t] = a0;
        outs[(n + 1) * 33 + t] = a1;
        outs[(n + 2) * 33 + t] = a2;
        outs[(n + 3) * 33 + t] = a3;
    }
    __syncthreads();

    // ---- coalesced final store: out[(b*HW + yx0 + t)*256 + n] ----
    for (int idx = tid; idx < TQ * DIMC; idx += 256) {
        const int t2 = idx >> 8;
        const int n  = idx & 255;
        out[(b * HWSZ + yx0 + t2) * DIMC + n] = outs[n * 33 + t2];
    }
}

// ---------------------------------------------------------------------------
extern "C" void kernel_launch(void* const* d_in, const int* in_sizes, int n_in,
                              void* d_out, int out_size) {
    const float* query = (const float*)d_in[0];
    const float* value = (const float*)d_in[1];
    const float* Wloc  = (const float*)d_in[2];
    const float* bloc  = (const float*)d_in[3];
    const float* Watt  = (const float*)d_in[4];
    const float* batt  = (const float*)d_in[5];
    const float* Wval  = (const float*)d_in[6];
    const float* bval  = (const float*)d_in[7];
    const float* Wout  = (const float*)d_in[8];
    const float* bout  = (const float*)d_in[9];
    float* out = (float*)d_out;

    const int smem1 = (256 * 33 * 2) * sizeof(float);                 // 67.6 KB
    const int smem2 = (256 * 33 + 192 * 32 + 256 * 33) * sizeof(float); // 92.2 KB
    cudaFuncSetAttribute(vproj_kernel, cudaFuncAttributeMaxDynamicSharedMemorySize, smem1);
    cudaFuncSetAttribute(fused_kernel, cudaFuncAttributeMaxDynamicSharedMemorySize, smem2);

    const int nblocks = (BB * HWSZ) / TQ;  // 512
    vproj_kernel<<<nblocks, 256, smem1>>>(value, Wval, bval);
    fused_kernel<<<nblocks, 256, smem2>>>(query, Wloc, bloc, Watt, batt, Wout, bout, out);
}

// round 3
// speedup vs baseline: 2.3606x; 2.3606x over previous
#include <cuda_runtime.h>
#include <math.h>

// Problem constants
#define BB   4
#define DIMC 256
#define HH   64
#define WW   64
#define HWSZ 4096
#define NHD  8
#define HDC  32
#define NPP  8

// GEMM tiling
#define BM 128
#define BN 128
#define KC 16

// Scratch (device globals: no allocation allowed)
__device__ float g_vp  [BB * NHD * HWSZ * HDC];   // v_proj, [b][h][yx][d]
__device__ float g_loc [BB * HWSZ * 128];         // loc logits, [g][128]
__device__ float g_att [BB * HWSZ * 64];          // att logits, [g][64]
__device__ float g_msda[DIMC * BB * HWSZ];        // msda out, k-major [k][g]

// smem layout (floats)
#define AS0  0
#define AS1  (KC * 128)
#define BS0  (2 * KC * 128)
#define BS1  (2 * KC * 128 + KC * 132)
#define CSO  (2 * KC * 128 + 2 * KC * 132)
#define SMEM_FLOATS (CSO + 128 * 68)

// DST: 0 = out GEMM (A = g_msda, C = param, ldc=256)
//      1 = loc  (C = g_loc, ldc=128)
//      2 = att  (C = g_att, ldc=64)
//      3 = vproj (C = g_vp special layout)
template<int DST>
__global__ __launch_bounds__(256, 2)
void gemm_kernel(const float* __restrict__ A, const float* __restrict__ Wt,
                 const float* __restrict__ bias, float* __restrict__ Cparam,
                 int N, int lda, int bsA, int ldc)
{
    extern __shared__ float sm[];
    const int tid = threadIdx.x;
    const int m0  = blockIdx.x * BM;
    const int n0  = blockIdx.y * BN;
    const int b   = m0 >> 12;
    const int yx0 = m0 & (HWSZ - 1);

    const float* Asrc = (DST == 0) ? g_msda : A;
    const float* gA   = Asrc + (size_t)b * bsA + yx0;
    float* C = (DST == 0) ? Cparam : (DST == 1) ? g_loc : (DST == 2) ? g_att : g_vp;

    const int tn = tid & 15;   // n-subtile
    const int tt = tid >> 4;   // t-subtile

    // load-index mapping
    const int ak = tid >> 5;          // A row within chunk (0..7)
    const int ac = (tid & 31) * 4;    // A col (token) 0..124
    const int wn = tid >> 2;          // W row 0..63
    const int wc = (tid & 3) * 4;     // W k-offset 0,4,8,12

    float4 pa0, pa1, pw0, pw1;
    const float4 z4 = make_float4(0.f, 0.f, 0.f, 0.f);

    // prefetch chunk 0
    pa0 = *(const float4*)(gA + (size_t)(ak    ) * lda + ac);
    pa1 = *(const float4*)(gA + (size_t)(ak + 8) * lda + ac);
    {
        const int n1 = n0 + wn, n2 = n0 + wn + 64;
        pw0 = (n1 < N) ? *(const float4*)(Wt + (size_t)n1 * DIMC + wc) : z4;
        pw1 = (n2 < N) ? *(const float4*)(Wt + (size_t)n2 * DIMC + wc) : z4;
    }
    {
        float* As = sm + AS0; float* Bs = sm + BS0;
        *(float4*)(As + ak * 128 + ac)       = pa0;
        *(float4*)(As + (ak + 8) * 128 + ac) = pa1;
        Bs[(wc + 0) * 132 + wn] = pw0.x; Bs[(wc + 1) * 132 + wn] = pw0.y;
        Bs[(wc + 2) * 132 + wn] = pw0.z; Bs[(wc + 3) * 132 + wn] = pw0.w;
        Bs[(wc + 0) * 132 + wn + 64] = pw1.x; Bs[(wc + 1) * 132 + wn + 64] = pw1.y;
        Bs[(wc + 2) * 132 + wn + 64] = pw1.z; Bs[(wc + 3) * 132 + wn + 64] = pw1.w;
    }
    __syncthreads();

    float acc[8][8];
    #pragma unroll
    for (int i = 0; i < 8; i++)
        #pragma unroll
        for (int j = 0; j < 8; j++) acc[i][j] = 0.f;

    int cur = 0;
    const int KITER = DIMC / KC;   // 16
    for (int kc = 0; kc < KITER; kc++) {
        if (kc + 1 < KITER) {
            const int kk = (kc + 1) * KC;
            pa0 = *(const float4*)(gA + (size_t)(kk + ak    ) * lda + ac);
            pa1 = *(const float4*)(gA + (size_t)(kk + ak + 8) * lda + ac);
            const int n1 = n0 + wn, n2 = n0 + wn + 64;
            pw0 = (n1 < N) ? *(const float4*)(Wt + (size_t)n1 * DIMC + kk + wc) : z4;
            pw1 = (n2 < N) ? *(const float4*)(Wt + (size_t)n2 * DIMC + kk + wc) : z4;
        }
        const float* As = sm + (cur ? AS1 : AS0);
        const float* Bs = sm + (cur ? BS1 : BS0);
        #pragma unroll
        for (int k = 0; k < KC; k++) {
            const float4 w0 = *(const float4*)(Bs + k * 132 + tn * 8);
            const float4 w1 = *(const float4*)(Bs + k * 132 + tn * 8 + 4);
            const float4 q0 = *(const float4*)(As + k * 128 + tt * 8);
            const float4 q1 = *(const float4*)(As + k * 128 + tt * 8 + 4);
            const float wv[8] = {w0.x, w0.y, w0.z, w0.w, w1.x, w1.y, w1.z, w1.w};
            const float qv[8] = {q0.x, q0.y, q0.z, q0.w, q1.x, q1.y, q1.z, q1.w};
            #pragma unroll
            for (int i = 0; i < 8; i++)
                #pragma unroll
                for (int j = 0; j < 8; j++)
                    acc[i][j] += wv[i] * qv[j];
        }
        if (kc + 1 < KITER) {
            float* Asn = sm + (cur ? AS0 : AS1);
            float* Bsn = sm + (cur ? BS0 : BS1);
            *(float4*)(Asn + ak * 128 + ac)       = pa0;
            *(float4*)(Asn + (ak + 8) * 128 + ac) = pa1;
            Bsn[(wc + 0) * 132 + wn] = pw0.x; Bsn[(wc + 1) * 132 + wn] = pw0.y;
            Bsn[(wc + 2) * 132 + wn] = pw0.z; Bsn[(wc + 3) * 132 + wn] = pw0.w;
            Bsn[(wc + 0) * 132 + wn + 64] = pw1.x; Bsn[(wc + 1) * 132 + wn + 64] = pw1.y;
            Bsn[(wc + 2) * 132 + wn + 64] = pw1.z; Bsn[(wc + 3) * 132 + wn + 64] = pw1.w;
            __syncthreads();
            cur ^= 1;
        }
    }

    // bias
    #pragma unroll
    for (int i = 0; i < 8; i++) {
        const int n = n0 + tn * 8 + i;
        const float bb = (n < N) ? bias[n] : 0.f;
        #pragma unroll
        for (int j = 0; j < 8; j++) acc[i][j] += bb;
    }

    // epilogue: stage through smem in two 64-wide n halves, store coalesced
    float* Cs = sm + CSO;
    #pragma unroll
    for (int half = 0; half < 2; half++) {
        __syncthreads();
        if ((tn >> 3) == half) {
            const int nl = (tn & 7) * 8;
            #pragma unroll
            for (int j = 0; j < 8; j++)
                #pragma unroll
                for (int i = 0; i < 8; i++)
                    Cs[(tt * 8 + j) * 68 + nl + i] = acc[i][j];
        }
        __syncthreads();
        const int hbase = n0 + half * 64;
        if (hbase < N) {
            if (DST != 3) {
                for (int idx = tid; idx < 2048; idx += 256) {
                    const int t  = idx >> 4;
                    const int nf = (idx & 15) * 4;
                    if (hbase + nf < N)
                        *(float4*)(C + (size_t)(m0 + t) * ldc + hbase + nf) =
                            *(const float4*)(Cs + t * 68 + nf);
                }
            } else {
                for (int idx = tid; idx < 2048; idx += 256) {
                    const int d4   = (idx & 7) * 4;
                    const int rem  = idx >> 3;
                    const int t    = rem & 127;
                    const int hh   = rem >> 7;
                    const int nloc = hh * 32 + d4;
                    const int n    = hbase + nloc;
                    const int h    = n >> 5;
                    *(float4*)(C + ((size_t)((b * NHD + h) * HWSZ) + yx0 + t) * HDC + (n & 31)) =
                        *(const float4*)(Cs + t * 68 + nloc);
                }
            }
        }
    }
}

// ---------------------------------------------------------------------------
// Sampling: softmax over points + bilinear gather, writes g_msda k-major
// Block: 32 tokens, 256 threads.
// ---------------------------------------------------------------------------
__global__ __launch_bounds__(256)
void sampling_kernel()
{
    __shared__ float satt[64 * 33];     // normalized att: [(h*8+p)][t]
    __shared__ float msda[256 * 33];    // [(h*32+d)][t]

    const int tid = threadIdx.x;
    const int g0  = blockIdx.x * 32;
    const int b   = g0 >> 12;
    const int w   = tid >> 5;
    const int lane = tid & 31;

    // softmax: thread = (head h, token t)
    {
        const int h = w;
        const int t = lane;
        float e[NPP];
        float m = -1e30f;
        #pragma unroll
        for (int p = 0; p < NPP; p++) {
            e[p] = g_att[(size_t)(g0 + t) * 64 + h * NPP + p];
            m = fmaxf(m, e[p]);
        }
        float s = 0.f;
        #pragma unroll
        for (int p = 0; p < NPP; p++) { e[p] = expf(e[p] - m); s += e[p]; }
        const float inv = 1.f / s;
        #pragma unroll
        for (int p = 0; p < NPP; p++) satt[(h * NPP + p) * 33 + t] = e[p] * inv;
    }
    __syncthreads();

    // sampling: warp per (token, head) pair, lane = channel d
    for (int pair = w; pair < 32 * NHD; pair += 8) {
        const int tt = pair >> 3;
        const int h  = pair & 7;
        const int d  = lane;
        const float* lptr = g_loc + (size_t)(g0 + tt) * 128 + h * 16;
        const float* vpb  = g_vp + (size_t)((b * NHD + h) * HWSZ) * HDC;
        float acc = 0.f;
        #pragma unroll
        for (int p = 0; p < NPP; p++) {
            const float lx = __ldg(lptr + 2 * p);
            const float ly = __ldg(lptr + 2 * p + 1);
            const float aw = satt[(h * NPP + p) * 33 + tt];
            const float x = lx * (float)WW - 0.5f;
            const float y = ly * (float)HH - 0.5f;
            const float xf = floorf(x), yf = floorf(y);
            const float wx = x - xf, wy = y - yf;
            const int x0 = (int)xf, y0 = (int)yf;
            const int x1 = x0 + 1,  y1 = y0 + 1;
            const bool vx0 = (x0 >= 0) && (x0 < WW);
            const bool vx1 = (x1 >= 0) && (x1 < WW);
            const bool vy0 = (y0 >= 0) && (y0 < HH);
            const bool vy1 = (y1 >= 0) && (y1 < HH);
            const float v00 = (vx0 && vy0) ? vpb[(y0 * WW + x0) * HDC + d] : 0.f;
            const float v01 = (vx1 && vy0) ? vpb[(y0 * WW + x1) * HDC + d] : 0.f;
            const float v10 = (vx0 && vy1) ? vpb[(y1 * WW + x0) * HDC + d] : 0.f;
            const float v11 = (vx1 && vy1) ? vpb[(y1 * WW + x1) * HDC + d] : 0.f;
            const float top = v00 * (1.f - wx) + v01 * wx;
            const float bot = v10 * (1.f - wx) + v11 * wx;
            acc += aw * (top * (1.f - wy) + bot * wy);
        }
        msda[(h * HDC + d) * 33 + tt] = acc;
    }
    __syncthreads();

    // store k-major: g_msda[k*16384 + g]
    for (int idx = tid; idx < 256 * 32; idx += 256) {
        const int k = idx >> 5;
        const int t = idx & 31;
        g_msda[(size_t)k * (BB * HWSZ) + g0 + t] = msda[k * 33 + t];
    }
}

// ---------------------------------------------------------------------------
extern "C" void kernel_launch(void* const* d_in, const int* in_sizes, int n_in,
                              void* d_out, int out_size) {
    const float* query = (const float*)d_in[0];
    const float* value = (const float*)d_in[1];
    const float* Wloc  = (const float*)d_in[2];
    const float* bloc  = (const float*)d_in[3];
    const float* Watt  = (const float*)d_in[4];
    const float* batt  = (const float*)d_in[5];
    const float* Wval  = (const float*)d_in[6];
    const float* bval  = (const float*)d_in[7];
    const float* Wout  = (const float*)d_in[8];
    const float* bout  = (const float*)d_in[9];
    float* out = (float*)d_out;

    const size_t smem = SMEM_FLOATS * sizeof(float);   // ~66.5 KB
    cudaFuncSetAttribute(gemm_kernel<0>, cudaFuncAttributeMaxDynamicSharedMemorySize, (int)smem);
    cudaFuncSetAttribute(gemm_kernel<1>, cudaFuncAttributeMaxDynamicSharedMemorySize, (int)smem);
    cudaFuncSetAttribute(gemm_kernel<2>, cudaFuncAttributeMaxDynamicSharedMemorySize, (int)smem);
    cudaFuncSetAttribute(gemm_kernel<3>, cudaFuncAttributeMaxDynamicSharedMemorySize, (int)smem);

    const int MBLK = (BB * HWSZ) / BM;        // 128
    const int qlda = HWSZ;                    // query/value: [b][k][4096]
    const int qbs  = DIMC * HWSZ;

    // loc: N=128
    gemm_kernel<1><<<dim3(MBLK, 1), 256, smem>>>(query, Wloc, bloc, nullptr, 128, qlda, qbs, 128);
    // att: N=64
    gemm_kernel<2><<<dim3(MBLK, 1), 256, smem>>>(query, Watt, batt, nullptr, 64, qlda, qbs, 64);
    // vproj: N=256, special layout
    gemm_kernel<3><<<dim3(MBLK, 2), 256, smem>>>(value, Wval, bval, nullptr, 256, qlda, qbs, 0);
    // sampling
    sampling_kernel<<<(BB * HWSZ) / 32, 256>>>();
    // out GEMM: A = g_msda (k-major, lda=16384, batch-stride 4096)
    gemm_kernel<0><<<dim3(MBLK, 2), 256, smem>>>(nullptr, Wout, bout, out, 256, BB * HWSZ, HWSZ, 256);
}

// round 9
// speedup vs baseline: 2.7134x; 1.1495x over previous
#include <cuda_runtime.h>
#include <cuda_bf16.h>
#include <math.h>
#include <cstdint>

// Problem constants
#define BB   4
#define DIMC 256
#define HH   64
#define WW   64
#define HWSZ 4096
#define NHD  8
#define HDC  32
#define NPP  8

// Scratch (device globals: no allocation allowed)
__device__ float g_vp  [BB * NHD * HWSZ * HDC];   // v_proj, [b][h][yx][d]
__device__ float g_loc [BB * HWSZ * 128];         // loc logits, token-major
__device__ float g_att [BB * HWSZ * 64];          // att logits, token-major
__device__ float g_msda[BB * HWSZ * DIMC];        // msda out, token-major [g][k]

// ---------------------------------------------------------------------------
// helpers (plain sm_103-compatible: ldmatrix + mma.sync only)
// ---------------------------------------------------------------------------
__device__ __forceinline__ uint32_t smem_u32(const void* p) {
    uint32_t a;
    asm("{ .reg .u64 t; cvta.to.shared.u64 t, %1; cvt.u32.u64 %0, t; }" : "=r"(a) : "l"(p));
    return a;
}
__device__ __forceinline__ void ldsm_x4(uint32_t (&r)[4], uint32_t addr) {
    asm volatile("ldmatrix.sync.aligned.m8n8.x4.shared.b16 {%0,%1,%2,%3}, [%4];"
        : "=r"(r[0]), "=r"(r[1]), "=r"(r[2]), "=r"(r[3]) : "r"(addr));
}
__device__ __forceinline__ void mma16816(float (&c)[4], const uint32_t (&a)[4],
                                         uint32_t b0, uint32_t b1) {
    asm volatile("mma.sync.aligned.m16n8k16.row.col.f32.bf16.bf16.f32 "
        "{%0,%1,%2,%3}, {%4,%5,%6,%7}, {%8,%9}, {%0,%1,%2,%3};"
        : "+f"(c[0]), "+f"(c[1]), "+f"(c[2]), "+f"(c[3])
        : "r"(a[0]), "r"(a[1]), "r"(a[2]), "r"(a[3]), "r"(b0), "r"(b1));
}

__device__ __forceinline__ void pack_hilo4(float4 v, uint2& hi, uint2& lo) {
    __nv_bfloat16 h0 = __float2bfloat16(v.x), h1 = __float2bfloat16(v.y);
    __nv_bfloat16 h2 = __float2bfloat16(v.z), h3 = __float2bfloat16(v.w);
    __nv_bfloat16 l0 = __float2bfloat16(v.x - __bfloat162float(h0));
    __nv_bfloat16 l1 = __float2bfloat16(v.y - __bfloat162float(h1));
    __nv_bfloat16 l2 = __float2bfloat16(v.z - __bfloat162float(h2));
    __nv_bfloat16 l3 = __float2bfloat16(v.w - __bfloat162float(h3));
    hi.x = ((uint32_t)__bfloat16_as_ushort(h1) << 16) | __bfloat16_as_ushort(h0);
    hi.y = ((uint32_t)__bfloat16_as_ushort(h3) << 16) | __bfloat16_as_ushort(h2);
    lo.x = ((uint32_t)__bfloat16_as_ushort(l1) << 16) | __bfloat16_as_ushort(l0);
    lo.y = ((uint32_t)__bfloat16_as_ushort(l3) << 16) | __bfloat16_as_ushort(l2);
}

// ---------------------------------------------------------------------------
// bf16-split tensor-core GEMM: D[m=128 tokens][n=NT] = A[m][256] . Wt[n][256]^T + bias
// DST: 0 = out GEMM (A = g_msda token-major, C = param, ldc=256)
//      1 = loc (A = query k-major, C = g_loc, ldc=128)
//      2 = att (A = query k-major, C = g_att, ldc=64)
//      3 = vp  (A = value k-major, C = g_vp per-head layout)
// K chunks of 64, double-buffered. smem planes: Ah(16K) Al(16K) Bh Bl.
// Both A and B smem are [row][k] k-contiguous -> non-trans ldmatrix for BOTH.
// ---------------------------------------------------------------------------
template<int DST, int NT>
__global__ __launch_bounds__((NT == 128) ? 256 : 128, 1)
void tc_gemm(const float* __restrict__ Ain, const float* __restrict__ Wt,
             const float* __restrict__ bias, float* __restrict__ Cout)
{
    constexpr int NTH  = (NT == 128) ? 256 : 128;
    constexpr int BUFB = 32768 + 2 * NT * 128;     // bytes per k-chunk buffer

    extern __shared__ char smraw[];
    const uint32_t sb    = smem_u32(smraw);
    const uint32_t sbase = (sb + 1023) & ~1023u;
    char* smc = smraw + (sbase - sb);

    const int tid  = threadIdx.x;
    const int lane = tid & 31;
    const int wid  = tid >> 5;
    const int wm   = wid & 1;        // 2 warp-rows (64 tokens each)
    const int wn   = wid >> 1;       // NT/32 warp-cols (32 cols each)

    const int m0  = blockIdx.x * 128;
    const int ny0 = blockIdx.y * NT;
    const int b   = m0 >> 12;
    const int yx0 = m0 & (HWSZ - 1);

    // ---- chunk loader: fp32 -> bf16 hi/lo planes, xor-swizzled rows of 128B ----
    auto load_chunk = [&](int c) {
        char* buf = smc + (c & 1) * BUFB;
        const int k0 = c * 64;
        if (DST == 0) {
            for (int idx = tid; idx < 2048; idx += NTH) {
                const int t = idx >> 4, k4 = (idx & 15) * 4;
                const float4 v = *(const float4*)(g_msda + (size_t)(m0 + t) * DIMC + k0 + k4);
                uint2 hi, lo; pack_hilo4(v, hi, lo);
                const uint32_t off = t * 128 + ((k4 * 2) ^ ((t & 7) << 4));
                *(uint2*)(buf + off)         = hi;
                *(uint2*)(buf + 16384 + off) = lo;
            }
        } else {
            const float* gA = Ain + (size_t)b * DIMC * HWSZ + yx0;
            for (int idx = tid; idx < 2048; idx += NTH) {
                const int k = idx >> 5, t4 = (idx & 31) * 4;
                const float4 v = *(const float4*)(gA + (size_t)(k0 + k) * HWSZ + t4);
                const float vv[4] = {v.x, v.y, v.z, v.w};
                #pragma unroll
                for (int j = 0; j < 4; j++) {
                    const int m = t4 + j;
                    const __nv_bfloat16 h = __float2bfloat16(vv[j]);
                    const __nv_bfloat16 l = __float2bfloat16(vv[j] - __bfloat162float(h));
                    const uint32_t off = m * 128 + ((k * 2) ^ ((m & 7) << 4));
                    *(unsigned short*)(buf + off)         = __bfloat16_as_ushort(h);
                    *(unsigned short*)(buf + 16384 + off) = __bfloat16_as_ushort(l);
                }
            }
        }
        for (int idx = tid; idx < NT * 16; idx += NTH) {
            const int n = idx >> 4, k4 = (idx & 15) * 4;
            const float4 v = *(const float4*)(Wt + (size_t)(ny0 + n) * DIMC + k0 + k4);
            uint2 hi, lo; pack_hilo4(v, hi, lo);
            const uint32_t off = n * 128 + ((k4 * 2) ^ ((n & 7) << 4));
            *(uint2*)(buf + 32768 + off)            = hi;
            *(uint2*)(buf + 32768 + NT * 128 + off) = lo;
        }
    };

    load_chunk(0);
    __syncthreads();

    float acc[4][4][4];
    #pragma unroll
    for (int i = 0; i < 4; i++)
        #pragma unroll
        for (int j = 0; j < 4; j++)
            #pragma unroll
            for (int q = 0; q < 4; q++) acc[i][j][q] = 0.f;

    const uint32_t khb = (lane >> 4) * 16;    // ldmatrix k-half (bytes)

    for (int c = 0; c < 4; c++) {
        const uint32_t bufb = sbase + (c & 1) * BUFB;
        #pragma unroll
        for (int ks = 0; ks < 4; ks++) {
            const uint32_t kb = ks * 32 + khb;   // k16 byte offset + k-half
            uint32_t bh[2][4], bl[2][4];
            #pragma unroll
            for (int np = 0; np < 2; np++) {
                const int nr = wn * 32 + np * 16 + (lane & 15);
                const uint32_t off = nr * 128 + (kb ^ ((nr & 7) << 4));
                ldsm_x4(bh[np], bufb + 32768 + off);               // NON-trans: smem is [n][k]
                ldsm_x4(bl[np], bufb + 32768 + NT * 128 + off);
            }
            #pragma unroll
            for (int mt = 0; mt < 4; mt++) {
                const int mr = wm * 64 + mt * 16 + (lane & 15);
                const uint32_t off = mr * 128 + (kb ^ ((mr & 7) << 4));
                uint32_t ahf[4], alf[4];
                ldsm_x4(ahf, bufb + off);
                ldsm_x4(alf, bufb + 16384 + off);
                #pragma unroll
                for (int nt = 0; nt < 4; nt++) {
                    const int np = nt >> 1, hf = nt & 1;
                    mma16816(acc[mt][nt], ahf, bh[np][hf], bh[np][2 + hf]);
                    mma16816(acc[mt][nt], alf, bh[np][hf], bh[np][2 + hf]);
                    mma16816(acc[mt][nt], ahf, bl[np][hf], bl[np][2 + hf]);
                }
            }
        }
        if (c < 3) {
            load_chunk(c + 1);
            __syncthreads();
        }
    }
    __syncthreads();

    // ---- epilogue: frags -> smem stage -> (+bias) coalesced global store ----
    constexpr int NTP = NT + 4;
    float* stage = (float*)smc;
    #pragma unroll
    for (int mt = 0; mt < 4; mt++) {
        const int r  = wm * 64 + mt * 16 + (lane >> 2);
        #pragma unroll
        for (int nt = 0; nt < 4; nt++) {
            const int cl = wn * 32 + nt * 8 + (lane & 3) * 2;
            stage[r * NTP + cl]           = acc[mt][nt][0];
            stage[r * NTP + cl + 1]       = acc[mt][nt][1];
            stage[(r + 8) * NTP + cl]     = acc[mt][nt][2];
            stage[(r + 8) * NTP + cl + 1] = acc[mt][nt][3];
        }
    }
    __syncthreads();

    for (int idx = tid; idx < 128 * (NT / 4); idx += NTH) {
        const int t  = idx / (NT / 4);
        const int c4 = (idx % (NT / 4)) * 4;
        const int n  = ny0 + c4;
        float4 v = *(const float4*)(stage + t * NTP + c4);
        const float4 bb4 = *(const float4*)(bias + n);
        v.x += bb4.x; v.y += bb4.y; v.z += bb4.z; v.w += bb4.w;
        if (DST == 3) {
            const int h = n >> 5, d = n & 31;
            *(float4*)(g_vp + ((size_t)((b * NHD + h) * HWSZ) + yx0 + t) * HDC + d) = v;
        } else {
            float* C = (DST == 0) ? Cout : (DST == 1) ? g_loc : g_att;
            const int ldc = (DST == 0) ? 256 : (DST == 1) ? 128 : 64;
            *(float4*)(C + (size_t)(m0 + t) * ldc + n) = v;
        }
    }
}

// ---------------------------------------------------------------------------
// Sampling: softmax + bilinear gather (float4 channels), writes g_msda [g][256]
// Block: 32 tokens, 256 threads (8 warps). Warp = 4 pairs x 8 channel-lanes.
// ---------------------------------------------------------------------------
__global__ __launch_bounds__(256)
void sampling_kernel()
{
    __shared__ float satt[64 * 33];      // normalized att: [(h*8+p)][t]
    __shared__ float smout[32 * 256];    // [t][h*32+d]

    const int tid  = threadIdx.x;
    const int g0   = blockIdx.x * 32;
    const int b    = g0 >> 12;
    const int w    = tid >> 5;
    const int lane = tid & 31;

    // softmax: thread = (head h = w, token t = lane)
    {
        const int h = w, t = lane;
        float e[NPP];
        float m = -1e30f;
        #pragma unroll
        for (int p = 0; p < NPP; p++) {
            e[p] = g_att[(size_t)(g0 + t) * 64 + h * NPP + p];
            m = fmaxf(m, e[p]);
        }
        float s = 0.f;
        #pragma unroll
        for (int p = 0; p < NPP; p++) { e[p] = expf(e[p] - m); s += e[p]; }
        const float inv = 1.f / s;
        #pragma unroll
        for (int p = 0; p < NPP; p++) satt[(h * NPP + p) * 33 + t] = e[p] * inv;
    }
    __syncthreads();

    const int sub = lane >> 3;          // pair within warp (0..3)
    const int d4  = (lane & 7) * 4;     // channel group

    for (int i = 0; i < 8; i++) {
        const int pair = w * 32 + i * 4 + sub;   // 0..255
        const int tt   = pair >> 3;
        const int h    = pair & 7;
        const float* lptr = g_loc + (size_t)(g0 + tt) * 128 + h * 16;
        const float* vpb  = g_vp + (size_t)((b * NHD + h) * HWSZ) * HDC;
        float4 acc = make_float4(0.f, 0.f, 0.f, 0.f);
        #pragma unroll
        for (int p = 0; p < NPP; p++) {
            const float lx = lptr[2 * p];
            const float ly = lptr[2 * p + 1];
            const float aw = satt[(h * NPP + p) * 33 + tt];
            const float x = lx * (float)WW - 0.5f;
            const float y = ly * (float)HH - 0.5f;
            const float xf = floorf(x), yf = floorf(y);
            const float wx = x - xf, wy = y - yf;
            const int x0 = (int)xf, y0 = (int)yf;
            const int x1 = x0 + 1,  y1 = y0 + 1;
            const bool vx0 = (x0 >= 0) & (x0 < WW);
            const bool vx1 = (x1 >= 0) & (x1 < WW);
            const bool vy0 = (y0 >= 0) & (y0 < HH);
            const bool vy1 = (y1 >= 0) & (y1 < HH);
            const float4 z = make_float4(0.f, 0.f, 0.f, 0.f);
            const float4 v00 = (vx0 && vy0) ? *(const float4*)(vpb + (y0 * WW + x0) * HDC + d4) : z;
            const float4 v01 = (vx1 && vy0) ? *(const float4*)(vpb + (y0 * WW + x1) * HDC + d4) : z;
            const float4 v10 = (vx0 && vy1) ? *(const float4*)(vpb + (y1 * WW + x0) * HDC + d4) : z;
            const float4 v11 = (vx1 && vy1) ? *(const float4*)(vpb + (y1 * WW + x1) * HDC + d4) : z;
            const float wa = aw * (1.f - wx) * (1.f - wy);
            const float wb = aw * wx * (1.f - wy);
            const float wc = aw * (1.f - wx) * wy;
            const float wd = aw * wx * wy;
            acc.x += wa * v00.x + wb * v01.x + wc * v10.x + wd * v11.x;
            acc.y += wa * v00.y + wb * v01.y + wc * v10.y + wd * v11.y;
            acc.z += wa * v00.z + wb * v01.z + wc * v10.z + wd * v11.z;
            acc.w += wa * v00.w + wb * v01.w + wc * v10.w + wd * v11.w;
        }
        *(float4*)(smout + tt * 256 + h * 32 + d4) = acc;
    }
    __syncthreads();

    // coalesced token-major write: g_msda[(g0+t)*256 + c]
    for (int idx = tid; idx < 32 * 64; idx += 256) {
        const int t = idx >> 6, c4 = (idx & 63) * 4;
        *(float4*)(g_msda + (size_t)(g0 + t) * DIMC + c4) = *(const float4*)(smout + t * 256 + c4);
    }
}

// ---------------------------------------------------------------------------
extern "C" void kernel_launch(void* const* d_in, const int* in_sizes, int n_in,
                              void* d_out, int out_size) {
    const float* query = (const float*)d_in[0];
    const float* value = (const float*)d_in[1];
    const float* Wloc  = (const float*)d_in[2];
    const float* bloc  = (const float*)d_in[3];
    const float* Watt  = (const float*)d_in[4];
    const float* batt  = (const float*)d_in[5];
    const float* Wval  = (const float*)d_in[6];
    const float* bval  = (const float*)d_in[7];
    const float* Wout  = (const float*)d_in[8];
    const float* bout  = (const float*)d_in[9];
    float* out = (float*)d_out;

    const int sm128 = 2 * (32768 + 2 * 128 * 128) + 1024;   // 132 KB
    const int sm64  = 2 * (32768 + 2 * 64 * 128) + 1024;    //  99 KB
    cudaFuncSetAttribute(tc_gemm<1, 128>, cudaFuncAttributeMaxDynamicSharedMemorySize, sm128);
    cudaFuncSetAttribute(tc_gemm<2, 64>,  cudaFuncAttributeMaxDynamicSharedMemorySize, sm64);
    cudaFuncSetAttribute(tc_gemm<3, 128>, cudaFuncAttributeMaxDynamicSharedMemorySize, sm128);
    cudaFuncSetAttribute(tc_gemm<0, 128>, cudaFuncAttributeMaxDynamicSharedMemorySize, sm128);

    const int MBLK = (BB * HWSZ) / 128;   // 128

    tc_gemm<1, 128><<<dim3(MBLK, 1), 256, sm128>>>(query, Wloc, bloc, nullptr);
    tc_gemm<2, 64> <<<dim3(MBLK, 1), 128, sm64>>> (query, Watt, batt, nullptr);
    tc_gemm<3, 128><<<dim3(MBLK, 2), 256, sm128>>>(value, Wval, bval, nullptr);
    sampling_kernel<<<(BB * HWSZ) / 32, 256>>>();
    tc_gemm<0, 128><<<dim3(MBLK, 2), 256, sm128>>>(nullptr, Wout, bout, out);
}

// round 10
// speedup vs baseline: 4.1331x; 1.5232x over previous
#include <cuda_runtime.h>
#include <cuda_bf16.h>
#include <math.h>
#include <cstdint>

// Problem constants
#define BB   4
#define DIMC 256
#define HH   64
#define WW   64
#define HWSZ 4096
#define NHD  8
#define HDC  32
#define NPP  8
#define NG   (BB * HWSZ)      // 16384 tokens

// ---------------------------------------------------------------------------
// Scratch (device globals: no allocation allowed)
// ---------------------------------------------------------------------------
__device__ __align__(16) unsigned short g_qh[NG * DIMC];   // query bf16 hi, token-major
__device__ __align__(16) unsigned short g_ql[NG * DIMC];   // query bf16 lo
__device__ __align__(16) unsigned short g_vh[NG * DIMC];   // value bf16 hi
__device__ __align__(16) unsigned short g_vl[NG * DIMC];   // value bf16 lo
__device__ __align__(16) unsigned short g_mh[NG * DIMC];   // msda bf16 hi
__device__ __align__(16) unsigned short g_ml[NG * DIMC];   // msda bf16 lo
__device__ __align__(16) unsigned short g_w1h[192 * DIMC]; // [Wloc;Watt] hi
__device__ __align__(16) unsigned short g_w1l[192 * DIMC];
__device__ __align__(16) unsigned short g_w3h[256 * DIMC]; // Wval hi
__device__ __align__(16) unsigned short g_w3l[256 * DIMC];
__device__ __align__(16) unsigned short g_w0h[256 * DIMC]; // Wout hi
__device__ __align__(16) unsigned short g_w0l[256 * DIMC];

__device__ float g_vp [BB * NHD * HWSZ * HDC];   // v_proj, [b][h][yx][d]
__device__ float g_loc[NG * 128];                // loc logits, token-major
__device__ float g_att[NG * 64];                 // att logits, token-major

// ---------------------------------------------------------------------------
// helpers (plain sm_103-compatible: ldmatrix + mma.sync only)
// ---------------------------------------------------------------------------
__device__ __forceinline__ uint32_t smem_u32(const void* p) {
    uint32_t a;
    asm("{ .reg .u64 t; cvta.to.shared.u64 t, %1; cvt.u32.u64 %0, t; }" : "=r"(a) : "l"(p));
    return a;
}
__device__ __forceinline__ void ldsm_x4(uint32_t (&r)[4], uint32_t addr) {
    asm volatile("ldmatrix.sync.aligned.m8n8.x4.shared.b16 {%0,%1,%2,%3}, [%4];"
        : "=r"(r[0]), "=r"(r[1]), "=r"(r[2]), "=r"(r[3]) : "r"(addr));
}
__device__ __forceinline__ void mma16816(float (&c)[4], const uint32_t (&a)[4],
                                         uint32_t b0, uint32_t b1) {
    asm volatile("mma.sync.aligned.m16n8k16.row.col.f32.bf16.bf16.f32 "
        "{%0,%1,%2,%3}, {%4,%5,%6,%7}, {%8,%9}, {%0,%1,%2,%3};"
        : "+f"(c[0]), "+f"(c[1]), "+f"(c[2]), "+f"(c[3])
        : "r"(a[0]), "r"(a[1]), "r"(a[2]), "r"(a[3]), "r"(b0), "r"(b1));
}

__device__ __forceinline__ void pack_hilo4(float4 v, uint2& hi, uint2& lo) {
    __nv_bfloat16 h0 = __float2bfloat16(v.x), h1 = __float2bfloat16(v.y);
    __nv_bfloat16 h2 = __float2bfloat16(v.z), h3 = __float2bfloat16(v.w);
    __nv_bfloat16 l0 = __float2bfloat16(v.x - __bfloat162float(h0));
    __nv_bfloat16 l1 = __float2bfloat16(v.y - __bfloat162float(h1));
    __nv_bfloat16 l2 = __float2bfloat16(v.z - __bfloat162float(h2));
    __nv_bfloat16 l3 = __float2bfloat16(v.w - __bfloat162float(h3));
    hi.x = ((uint32_t)__bfloat16_as_ushort(h1) << 16) | __bfloat16_as_ushort(h0);
    hi.y = ((uint32_t)__bfloat16_as_ushort(h3) << 16) | __bfloat16_as_ushort(h2);
    lo.x = ((uint32_t)__bfloat16_as_ushort(l1) << 16) | __bfloat16_as_ushort(l0);
    lo.y = ((uint32_t)__bfloat16_as_ushort(l3) << 16) | __bfloat16_as_ushort(l2);
}

// ---------------------------------------------------------------------------
// convert_act: transpose query/value [b][k][4096] fp32 -> token-major bf16 hi/lo
// grid 1024: [tensor(2)][b(4)][tile(128)], 256 threads, tile = 32 tokens
// ---------------------------------------------------------------------------
__global__ __launch_bounds__(256)
void convert_act(const float* __restrict__ q, const float* __restrict__ v)
{
    __shared__ float sm[256 * 33];
    const int bi = blockIdx.x;
    const int tensor = bi >> 9;
    const int rem = bi & 511;
    const int b = rem >> 7, tile = rem & 127;
    const float* src = (tensor ? v : q) + (size_t)b * DIMC * HWSZ + tile * 32;

    for (int idx = threadIdx.x; idx < 2048; idx += 256) {
        const int k = idx >> 3, t4 = (idx & 7) * 4;
        const float4 val = *(const float4*)(src + (size_t)k * HWSZ + t4);
        sm[k * 33 + t4 + 0] = val.x;
        sm[k * 33 + t4 + 1] = val.y;
        sm[k * 33 + t4 + 2] = val.z;
        sm[k * 33 + t4 + 3] = val.w;
    }
    __syncthreads();

    unsigned short* dh = tensor ? g_vh : g_qh;
    unsigned short* dl = tensor ? g_vl : g_ql;
    const size_t g0 = (size_t)b * HWSZ + tile * 32;

    for (int idx = threadIdx.x; idx < 1024; idx += 256) {
        const int t = idx >> 5, k8 = (idx & 31) * 8;
        float4 v0, v1;
        v0.x = sm[(k8 + 0) * 33 + t]; v0.y = sm[(k8 + 1) * 33 + t];
        v0.z = sm[(k8 + 2) * 33 + t]; v0.w = sm[(k8 + 3) * 33 + t];
        v1.x = sm[(k8 + 4) * 33 + t]; v1.y = sm[(k8 + 5) * 33 + t];
        v1.z = sm[(k8 + 6) * 33 + t]; v1.w = sm[(k8 + 7) * 33 + t];
        uint2 h0, l0, h1, l1;
        pack_hilo4(v0, h0, l0); pack_hilo4(v1, h1, l1);
        *(uint4*)(dh + (g0 + t) * DIMC + k8) = make_uint4(h0.x, h0.y, h1.x, h1.y);
        *(uint4*)(dl + (g0 + t) * DIMC + k8) = make_uint4(l0.x, l0.y, l1.x, l1.y);
    }
}

// ---------------------------------------------------------------------------
// convert_w: weights fp32 -> bf16 hi/lo planes (no transpose needed)
// 704 rows total: [0,192) = Wloc|Watt -> g_w1, [192,448) = Wval, [448,704) = Wout
// ---------------------------------------------------------------------------
__global__ __launch_bounds__(256)
void convert_w(const float* __restrict__ Wloc, const float* __restrict__ Watt,
               const float* __restrict__ Wval, const float* __restrict__ Wout)
{
    const int idx = blockIdx.x * 256 + threadIdx.x;   // one item = 8 elements
    if (idx >= 704 * 32) return;
    const int r = idx >> 5, k8 = (idx & 31) * 8;
    const float* src;
    unsigned short *dh, *dl;
    if (r < 192) {
        src = (r < 128) ? (Wloc + (size_t)r * DIMC) : (Watt + (size_t)(r - 128) * DIMC);
        dh = g_w1h + (size_t)r * DIMC; dl = g_w1l + (size_t)r * DIMC;
    } else if (r < 448) {
        const int rr = r - 192;
        src = Wval + (size_t)rr * DIMC;
        dh = g_w3h + (size_t)rr * DIMC; dl = g_w3l + (size_t)rr * DIMC;
    } else {
        const int rr = r - 448;
        src = Wout + (size_t)rr * DIMC;
        dh = g_w0h + (size_t)rr * DIMC; dl = g_w0l + (size_t)rr * DIMC;
    }
    const float4 v0 = *(const float4*)(src + k8);
    const float4 v1 = *(const float4*)(src + k8 + 4);
    uint2 h0, l0, h1, l1;
    pack_hilo4(v0, h0, l0); pack_hilo4(v1, h1, l1);
    *(uint4*)(dh + k8) = make_uint4(h0.x, h0.y, h1.x, h1.y);
    *(uint4*)(dl + k8) = make_uint4(l0.x, l0.y, l1.x, l1.y);
}

// ---------------------------------------------------------------------------
// bf16-split tensor-core GEMM: D[m=128 tokens][n=NT] = A[m][256] . W[n][256]^T + bias
// DST: 1 = loc+att merged (NT=192): n<128 -> g_loc, else g_att
//      3 = vproj (NT=256): C = g_vp per-head layout
//      0 = out   (NT=256): C = Cout, ldc=256
// K chunks of 64, double-buffered. All operands pre-converted bf16 hi/lo planes.
// ---------------------------------------------------------------------------
template<int DST, int NT>
__global__ __launch_bounds__((NT == 256) ? 512 : 384, 1)
void tc_gemm(const float* __restrict__ bias1, const float* __restrict__ bias2,
             float* __restrict__ Cout)
{
    constexpr int NTH  = (NT == 256) ? 512 : 384;
    constexpr int BUFB = 32768 + 2 * NT * 128;     // Ah(16K) Al(16K) Bh Bl

    extern __shared__ char smraw[];
    const uint32_t sb    = smem_u32(smraw);
    const uint32_t sbase = (sb + 1023) & ~1023u;
    char* smc = smraw + (sbase - sb);

    const int tid  = threadIdx.x;
    const int lane = tid & 31;
    const int wid  = tid >> 5;
    const int wm   = wid & 1;        // 2 warp-rows (64 tokens each)
    const int wn   = wid >> 1;       // NT/32 warp-cols (32 cols each)

    const int m0  = blockIdx.x * 128;
    const int b   = m0 >> 12;
    const int yx0 = m0 & (HWSZ - 1);

    const char* Ah = (const char*)((DST == 1) ? g_qh : (DST == 3) ? g_vh : g_mh);
    const char* Al = (const char*)((DST == 1) ? g_ql : (DST == 3) ? g_vl : g_ml);
    const char* Wh = (const char*)((DST == 1) ? g_w1h : (DST == 3) ? g_w3h : g_w0h);
    const char* Wl = (const char*)((DST == 1) ? g_w1l : (DST == 3) ? g_w3l : g_w0l);

    // ---- chunk loader: pure LDG.128 -> swizzled STS.128, conflict-free ----
    auto load_chunk = [&](int c) {
        char* buf = smc + (c & 1) * BUFB;
        const int kB = c * 128;   // chunk byte offset within a 512B row
        for (int idx = tid; idx < 128 * 8; idx += NTH) {
            const int t = idx >> 3, ko = idx & 7;
            const size_t go = (size_t)(m0 + t) * 512 + kB + ko * 16;
            const uint4 h = *(const uint4*)(Ah + go);
            const uint4 l = *(const uint4*)(Al + go);
            const uint32_t off = t * 128 + ((ko * 16) ^ ((t & 7) << 4));
            *(uint4*)(buf + off)         = h;
            *(uint4*)(buf + 16384 + off) = l;
        }
        for (int idx = tid; idx < NT * 8; idx += NTH) {
            const int n = idx >> 3, ko = idx & 7;
            const size_t go = (size_t)n * 512 + kB + ko * 16;
            const uint4 h = *(const uint4*)(Wh + go);
            const uint4 l = *(const uint4*)(Wl + go);
            const uint32_t off = n * 128 + ((ko * 16) ^ ((n & 7) << 4));
            *(uint4*)(buf + 32768 + off)            = h;
            *(uint4*)(buf + 32768 + NT * 128 + off) = l;
        }
    };

    load_chunk(0);
    __syncthreads();

    float acc[4][4][4];
    #pragma unroll
    for (int i = 0; i < 4; i++)
        #pragma unroll
        for (int j = 0; j < 4; j++)
            #pragma unroll
            for (int q = 0; q < 4; q++) acc[i][j][q] = 0.f;

    const uint32_t khb = (lane >> 4) * 16;    // ldmatrix k-half (bytes)

    for (int c = 0; c < 4; c++) {
        const uint32_t bufb = sbase + (c & 1) * BUFB;
        #pragma unroll
        for (int ks = 0; ks < 4; ks++) {
            const uint32_t kb = ks * 32 + khb;
            uint32_t bh[2][4], bl[2][4];
            #pragma unroll
            for (int np = 0; np < 2; np++) {
                const int nr = wn * 32 + np * 16 + (lane & 15);
                const uint32_t off = nr * 128 + (kb ^ ((nr & 7) << 4));
                ldsm_x4(bh[np], bufb + 32768 + off);
                ldsm_x4(bl[np], bufb + 32768 + NT * 128 + off);
            }
            #pragma unroll
            for (int mt = 0; mt < 4; mt++) {
                const int mr = wm * 64 + mt * 16 + (lane & 15);
                const uint32_t off = mr * 128 + (kb ^ ((mr & 7) << 4));
                uint32_t ahf[4], alf[4];
                ldsm_x4(ahf, bufb + off);
                ldsm_x4(alf, bufb + 16384 + off);
                #pragma unroll
                for (int nt = 0; nt < 4; nt++) {
                    const int np = nt >> 1, hf = nt & 1;
                    mma16816(acc[mt][nt], ahf, bh[np][hf], bh[np][2 + hf]);
                    mma16816(acc[mt][nt], alf, bh[np][hf], bh[np][2 + hf]);
                    mma16816(acc[mt][nt], ahf, bl[np][hf], bl[np][2 + hf]);
                }
            }
        }
        if (c < 3) {
            load_chunk(c + 1);
            __syncthreads();
        }
    }
    __syncthreads();

    // ---- epilogue: frags -> smem stage -> (+bias) coalesced global store ----
    constexpr int NTP = NT + 4;
    float* stage = (float*)smc;
    #pragma unroll
    for (int mt = 0; mt < 4; mt++) {
        const int r = wm * 64 + mt * 16 + (lane >> 2);
        #pragma unroll
        for (int nt = 0; nt < 4; nt++) {
            const int cl = wn * 32 + nt * 8 + (lane & 3) * 2;
            stage[r * NTP + cl]           = acc[mt][nt][0];
            stage[r * NTP + cl + 1]       = acc[mt][nt][1];
            stage[(r + 8) * NTP + cl]     = acc[mt][nt][2];
            stage[(r + 8) * NTP + cl + 1] = acc[mt][nt][3];
        }
    }
    __syncthreads();

    for (int idx = tid; idx < 128 * (NT / 4); idx += NTH) {
        const int t  = idx / (NT / 4);
        const int n  = (idx % (NT / 4)) * 4;
        float4 v = *(const float4*)(stage + t * NTP + n);
        const float4 bb4 = (DST == 1 && n >= 128)
            ? *(const float4*)(bias2 + (n - 128))
            : *(const float4*)(bias1 + n);
        v.x += bb4.x; v.y += bb4.y; v.z += bb4.z; v.w += bb4.w;
        if (DST == 3) {
            const int h = n >> 5, d = n & 31;
            *(float4*)(g_vp + ((size_t)((b * NHD + h) * HWSZ) + yx0 + t) * HDC + d) = v;
        } else if (DST == 1) {
            if (n < 128) *(float4*)(g_loc + (size_t)(m0 + t) * 128 + n) = v;
            else         *(float4*)(g_att + (size_t)(m0 + t) * 64 + (n - 128)) = v;
        } else {
            *(float4*)(Cout + (size_t)(m0 + t) * 256 + n) = v;
        }
    }
}

// ---------------------------------------------------------------------------
// Sampling: softmax + bilinear gather, writes g_mh/g_ml bf16 planes [g][256]
// Block: 32 tokens, 256 threads (8 warps). Warp = 4 pairs x 8 channel-lanes.
// ---------------------------------------------------------------------------
__global__ __launch_bounds__(256)
void sampling_kernel()
{
    __shared__ float satt[64 * 33];      // normalized att: [(h*8+p)][t]
    __shared__ float smout[32 * 256];    // [t][h*32+d]

    const int tid  = threadIdx.x;
    const int g0   = blockIdx.x * 32;
    const int b    = g0 >> 12;
    const int w    = tid >> 5;
    const int lane = tid & 31;

    // softmax: thread = (head h = w, token t = lane)
    {
        const int h = w, t = lane;
        float e[NPP];
        float m = -1e30f;
        #pragma unroll
        for (int p = 0; p < NPP; p++) {
            e[p] = g_att[(size_t)(g0 + t) * 64 + h * NPP + p];
            m = fmaxf(m, e[p]);
        }
        float s = 0.f;
        #pragma unroll
        for (int p = 0; p < NPP; p++) { e[p] = expf(e[p] - m); s += e[p]; }
        const float inv = 1.f / s;
        #pragma unroll
        for (int p = 0; p < NPP; p++) satt[(h * NPP + p) * 33 + t] = e[p] * inv;
    }
    __syncthreads();

    const int sub = lane >> 3;          // pair within warp (0..3)
    const int d4  = (lane & 7) * 4;     // channel group

    for (int i = 0; i < 8; i++) {
        const int pair = w * 32 + i * 4 + sub;   // 0..255
        const int tt   = pair >> 3;
        const int h    = pair & 7;
        const float* lptr = g_loc + (size_t)(g0 + tt) * 128 + h * 16;
        const float* vpb  = g_vp + (size_t)((b * NHD + h) * HWSZ) * HDC;
        float4 acc = make_float4(0.f, 0.f, 0.f, 0.f);
        #pragma unroll
        for (int p = 0; p < NPP; p++) {
            const float lx = lptr[2 * p];
            const float ly = lptr[2 * p + 1];
            const float aw = satt[(h * NPP + p) * 33 + tt];
            const float x = lx * (float)WW - 0.5f;
            const float y = ly * (float)HH - 0.5f;
            const float xf = floorf(x), yf = floorf(y);
            const float wx = x - xf, wy = y - yf;
            const int x0 = (int)xf, y0 = (int)yf;
            const int x1 = x0 + 1,  y1 = y0 + 1;
            const bool vx0 = (x0 >= 0) & (x0 < WW);
            const bool vx1 = (x1 >= 0) & (x1 < WW);
            const bool vy0 = (y0 >= 0) & (y0 < HH);
            const bool vy1 = (y1 >= 0) & (y1 < HH);
            const float4 z = make_float4(0.f, 0.f, 0.f, 0.f);
            const float4 v00 = (vx0 && vy0) ? *(const float4*)(vpb + (y0 * WW + x0) * HDC + d4) : z;
            const float4 v01 = (vx1 && vy0) ? *(const float4*)(vpb + (y0 * WW + x1) * HDC + d4) : z;
            const float4 v10 = (vx0 && vy1) ? *(const float4*)(vpb + (y1 * WW + x0) * HDC + d4) : z;
            const float4 v11 = (vx1 && vy1) ? *(const float4*)(vpb + (y1 * WW + x1) * HDC + d4) : z;
            const float wa = aw * (1.f - wx) * (1.f - wy);
            const float wb = aw * wx * (1.f - wy);
            const float wc = aw * (1.f - wx) * wy;
            const float wd = aw * wx * wy;
            acc.x += wa * v00.x + wb * v01.x + wc * v10.x + wd * v11.x;
            acc.y += wa * v00.y + wb * v01.y + wc * v10.y + wd * v11.y;
            acc.z += wa * v00.z + wb * v01.z + wc * v10.z + wd * v11.z;
            acc.w += wa * v00.w + wb * v01.w + wc * v10.w + wd * v11.w;
        }
        *(float4*)(smout + tt * 256 + h * 32 + d4) = acc;
    }
    __syncthreads();

    // convert + coalesced token-major write of bf16 hi/lo planes
    for (int idx = tid; idx < 32 * 32; idx += 256) {
        const int t = idx >> 5, k8 = (idx & 31) * 8;
        const float4 v0 = *(const float4*)(smout + t * 256 + k8);
        const float4 v1 = *(const float4*)(smout + t * 256 + k8 + 4);
        uint2 h0, l0, h1, l1;
        pack_hilo4(v0, h0, l0); pack_hilo4(v1, h1, l1);
        *(uint4*)(g_mh + (size_t)(g0 + t) * DIMC + k8) = make_uint4(h0.x, h0.y, h1.x, h1.y);
        *(uint4*)(g_ml + (size_t)(g0 + t) * DIMC + k8) = make_uint4(l0.x, l0.y, l1.x, l1.y);
    }
}

// ---------------------------------------------------------------------------
extern "C" void kernel_launch(void* const* d_in, const int* in_sizes, int n_in,
                              void* d_out, int out_size) {
    const float* query = (const float*)d_in[0];
    const float* value = (const float*)d_in[1];
    const float* Wloc  = (const float*)d_in[2];
    const float* bloc  = (const float*)d_in[3];
    const float* Watt  = (const float*)d_in[4];
    const float* batt  = (const float*)d_in[5];
    const float* Wval  = (const float*)d_in[6];
    const float* bval  = (const float*)d_in[7];
    const float* Wout  = (const float*)d_in[8];
    const float* bout  = (const float*)d_in[9];
    float* out = (float*)d_out;

    const int sm192 = 2 * (32768 + 2 * 192 * 128) + 1024;   // ~161 KB
    const int sm256 = 2 * (32768 + 2 * 256 * 128) + 1024;   // ~197 KB
    cudaFuncSetAttribute(tc_gemm<1, 192>, cudaFuncAttributeMaxDynamicSharedMemorySize, sm192);
    cudaFuncSetAttribute(tc_gemm<3, 256>, cudaFuncAttributeMaxDynamicSharedMemorySize, sm256);
    cudaFuncSetAttribute(tc_gemm<0, 256>, cudaFuncAttributeMaxDynamicSharedMemorySize, sm256);

    const int MBLK = NG / 128;   // 128 CTAs

    convert_act<<<1024, 256>>>(query, value);
    convert_w<<<88, 256>>>(Wloc, Watt, Wval, Wout);
    tc_gemm<1, 192><<<MBLK, 384, sm192>>>(bloc, batt, nullptr);
    tc_gemm<3, 256><<<MBLK, 512, sm256>>>(bval, nullptr, nullptr);
    sampling_kernel<<<NG / 32, 256>>>();
    tc_gemm<0, 256><<<MBLK, 512, sm256>>>(bout, nullptr, out);
}

// round 13
// speedup vs baseline: 4.3025x; 1.0410x over previous
#include <cuda_runtime.h>
#include <cuda_bf16.h>
#include <math.h>
#include <cstdint>

// Problem constants
#define BB   4
#define DIMC 256
#define HH   64
#define WW   64
#define HWSZ 4096
#define NHD  8
#define HDC  32
#define NPP  8
#define NG   (BB * HWSZ)      // 16384 tokens

// ---------------------------------------------------------------------------
// Scratch (device globals: no allocation allowed)
// ---------------------------------------------------------------------------
__device__ __align__(16) unsigned short g_qh[NG * DIMC];   // query bf16 hi, token-major
__device__ __align__(16) unsigned short g_ql[NG * DIMC];   // query bf16 lo
__device__ __align__(16) unsigned short g_vh[NG * DIMC];   // value bf16 hi
__device__ __align__(16) unsigned short g_vl[NG * DIMC];   // value bf16 lo
__device__ __align__(16) unsigned short g_mh[NG * DIMC];   // msda bf16 hi
__device__ __align__(16) unsigned short g_ml[NG * DIMC];   // msda bf16 lo
__device__ __align__(16) unsigned short g_w1h[192 * DIMC]; // [Wloc;Watt] hi
__device__ __align__(16) unsigned short g_w1l[192 * DIMC];
__device__ __align__(16) unsigned short g_w3h[256 * DIMC]; // Wval hi
__device__ __align__(16) unsigned short g_w3l[256 * DIMC];
__device__ __align__(16) unsigned short g_w0h[256 * DIMC]; // Wout hi
__device__ __align__(16) unsigned short g_w0l[256 * DIMC];

__device__ float g_vp [BB * NHD * HWSZ * HDC];   // v_proj, [b][h][yx][d]
__device__ float g_loc[NG * 128];                // loc logits, token-major
__device__ float g_att[NG * 64];                 // att logits, token-major

// ---------------------------------------------------------------------------
// helpers (plain sm_103-compatible: ldmatrix + mma.sync + cp.async)
// ---------------------------------------------------------------------------
__device__ __forceinline__ uint32_t smem_u32(const void* p) {
    uint32_t a;
    asm("{ .reg .u64 t; cvta.to.shared.u64 t, %1; cvt.u32.u64 %0, t; }" : "=r"(a) : "l"(p));
    return a;
}
__device__ __forceinline__ void ldsm_x4(uint32_t (&r)[4], uint32_t addr) {
    asm volatile("ldmatrix.sync.aligned.m8n8.x4.shared.b16 {%0,%1,%2,%3}, [%4];"
        : "=r"(r[0]), "=r"(r[1]), "=r"(r[2]), "=r"(r[3]) : "r"(addr));
}
__device__ __forceinline__ void mma16816(float (&c)[4], const uint32_t (&a)[4],
                                         uint32_t b0, uint32_t b1) {
    asm volatile("mma.sync.aligned.m16n8k16.row.col.f32.bf16.bf16.f32 "
        "{%0,%1,%2,%3}, {%4,%5,%6,%7}, {%8,%9}, {%0,%1,%2,%3};"
        : "+f"(c[0]), "+f"(c[1]), "+f"(c[2]), "+f"(c[3])
        : "r"(a[0]), "r"(a[1]), "r"(a[2]), "r"(a[3]), "r"(b0), "r"(b1));
}
#define CP16(dst_u32, src_ptr) \
    asm volatile("cp.async.cg.shared.global [%0], [%1], 16;" :: "r"(dst_u32), "l"(src_ptr))
#define CP_COMMIT() asm volatile("cp.async.commit_group;" ::: "memory")
#define CP_WAIT0()  asm volatile("cp.async.wait_group 0;" ::: "memory")

__device__ __forceinline__ void pack_hilo4(float4 v, uint2& hi, uint2& lo) {
    __nv_bfloat16 h0 = __float2bfloat16(v.x), h1 = __float2bfloat16(v.y);
    __nv_bfloat16 h2 = __float2bfloat16(v.z), h3 = __float2bfloat16(v.w);
    __nv_bfloat16 l0 = __float2bfloat16(v.x - __bfloat162float(h0));
    __nv_bfloat16 l1 = __float2bfloat16(v.y - __bfloat162float(h1));
    __nv_bfloat16 l2 = __float2bfloat16(v.z - __bfloat162float(h2));
    __nv_bfloat16 l3 = __float2bfloat16(v.w - __bfloat162float(h3));
    hi.x = ((uint32_t)__bfloat16_as_ushort(h1) << 16) | __bfloat16_as_ushort(h0);
    hi.y = ((uint32_t)__bfloat16_as_ushort(h3) << 16) | __bfloat16_as_ushort(h2);
    lo.x = ((uint32_t)__bfloat16_as_ushort(l1) << 16) | __bfloat16_as_ushort(l0);
    lo.y = ((uint32_t)__bfloat16_as_ushort(l3) << 16) | __bfloat16_as_ushort(l2);
}

// ---------------------------------------------------------------------------
// convert_act: transpose query/value [b][k][4096] fp32 -> token-major bf16 hi/lo
// ---------------------------------------------------------------------------
__global__ __launch_bounds__(256)
void convert_act(const float* __restrict__ q, const float* __restrict__ v)
{
    __shared__ float sm[256 * 33];
    const int bi = blockIdx.x;
    const int tensor = bi >> 9;
    const int rem = bi & 511;
    const int b = rem >> 7, tile = rem & 127;
    const float* src = (tensor ? v : q) + (size_t)b * DIMC * HWSZ + tile * 32;

    for (int idx = threadIdx.x; idx < 2048; idx += 256) {
        const int k = idx >> 3, t4 = (idx & 7) * 4;
        const float4 val = *(const float4*)(src + (size_t)k * HWSZ + t4);
        sm[k * 33 + t4 + 0] = val.x;
        sm[k * 33 + t4 + 1] = val.y;
        sm[k * 33 + t4 + 2] = val.z;
        sm[k * 33 + t4 + 3] = val.w;
    }
    __syncthreads();

    unsigned short* dh = tensor ? g_vh : g_qh;
    unsigned short* dl = tensor ? g_vl : g_ql;
    const size_t g0 = (size_t)b * HWSZ + tile * 32;

    for (int idx = threadIdx.x; idx < 1024; idx += 256) {
        const int t = idx >> 5, k8 = (idx & 31) * 8;
        float4 v0, v1;
        v0.x = sm[(k8 + 0) * 33 + t]; v0.y = sm[(k8 + 1) * 33 + t];
        v0.z = sm[(k8 + 2) * 33 + t]; v0.w = sm[(k8 + 3) * 33 + t];
        v1.x = sm[(k8 + 4) * 33 + t]; v1.y = sm[(k8 + 5) * 33 + t];
        v1.z = sm[(k8 + 6) * 33 + t]; v1.w = sm[(k8 + 7) * 33 + t];
        uint2 h0, l0, h1, l1;
        pack_hilo4(v0, h0, l0); pack_hilo4(v1, h1, l1);
        *(uint4*)(dh + (g0 + t) * DIMC + k8) = make_uint4(h0.x, h0.y, h1.x, h1.y);
        *(uint4*)(dl + (g0 + t) * DIMC + k8) = make_uint4(l0.x, l0.y, l1.x, l1.y);
    }
}

// ---------------------------------------------------------------------------
// convert_w: weights fp32 -> bf16 hi/lo planes
// ---------------------------------------------------------------------------
__global__ __launch_bounds__(256)
void convert_w(const float* __restrict__ Wloc, const float* __restrict__ Watt,
               const float* __restrict__ Wval, const float* __restrict__ Wout)
{
    const int idx = blockIdx.x * 256 + threadIdx.x;
    if (idx >= 704 * 32) return;
    const int r = idx >> 5, k8 = (idx & 31) * 8;
    const float* src;
    unsigned short *dh, *dl;
    if (r < 192) {
        src = (r < 128) ? (Wloc + (size_t)r * DIMC) : (Watt + (size_t)(r - 128) * DIMC);
        dh = g_w1h + (size_t)r * DIMC; dl = g_w1l + (size_t)r * DIMC;
    } else if (r < 448) {
        const int rr = r - 192;
        src = Wval + (size_t)rr * DIMC;
        dh = g_w3h + (size_t)rr * DIMC; dl = g_w3l + (size_t)rr * DIMC;
    } else {
        const int rr = r - 448;
        src = Wout + (size_t)rr * DIMC;
        dh = g_w0h + (size_t)rr * DIMC; dl = g_w0l + (size_t)rr * DIMC;
    }
    const float4 v0 = *(const float4*)(src + k8);
    const float4 v1 = *(const float4*)(src + k8 + 4);
    uint2 h0, l0, h1, l1;
    pack_hilo4(v0, h0, l0); pack_hilo4(v1, h1, l1);
    *(uint4*)(dh + k8) = make_uint4(h0.x, h0.y, h1.x, h1.y);
    *(uint4*)(dl + k8) = make_uint4(l0.x, l0.y, l1.x, l1.y);
}

// ---------------------------------------------------------------------------
// bf16-split tensor-core GEMM with cp.async pipelined chunk loads.
// D[m=128][n=NT] = A[m][256].W[n][256]^T + bias
// ---------------------------------------------------------------------------
template<int DST, int NT>
__global__ __launch_bounds__((NT == 256) ? 512 : 384, 1)
void tc_gemm(const float* __restrict__ bias1, const float* __restrict__ bias2,
             float* __restrict__ Cout)
{
    constexpr int NTH  = (NT == 256) ? 512 : 384;
    constexpr int BUFB = 32768 + 2 * NT * 128;     // Ah(16K) Al(16K) Bh Bl

    extern __shared__ char smraw[];
    const uint32_t sb    = smem_u32(smraw);
    const uint32_t sbase = (sb + 1023) & ~1023u;
    char* smc = smraw + (sbase - sb);

    const int tid  = threadIdx.x;
    const int lane = tid & 31;
    const int wid  = tid >> 5;
    const int wm   = wid & 1;
    const int wn   = wid >> 1;

    const int m0  = blockIdx.x * 128;
    const int b   = m0 >> 12;
    const int yx0 = m0 & (HWSZ - 1);

    const char* Ah = (const char*)((DST == 1) ? g_qh : (DST == 3) ? g_vh : g_mh);
    const char* Al = (const char*)((DST == 1) ? g_ql : (DST == 3) ? g_vl : g_ml);
    const char* Wh = (const char*)((DST == 1) ? g_w1h : (DST == 3) ? g_w3h : g_w0h);
    const char* Wl = (const char*)((DST == 1) ? g_w1l : (DST == 3) ? g_w3l : g_w0l);

    // ---- async chunk loader: LDGSTS, conflict-free swizzled dst ----
    auto load_chunk_async = [&](int c) {
        const uint32_t bufb = sbase + (c & 1) * BUFB;
        const int kB = c * 128;
        for (int idx = tid; idx < 1024; idx += NTH) {
            const int t = idx >> 3, ko = idx & 7;
            const size_t go = (size_t)(m0 + t) * 512 + kB + ko * 16;
            const uint32_t off = t * 128 + ((ko * 16) ^ ((t & 7) << 4));
            CP16(bufb + off, Ah + go);
            CP16(bufb + 16384 + off, Al + go);
        }
        for (int idx = tid; idx < NT * 8; idx += NTH) {
            const int n = idx >> 3, ko = idx & 7;
            const size_t go = (size_t)n * 512 + kB + ko * 16;
            const uint32_t off = n * 128 + ((ko * 16) ^ ((n & 7) << 4));
            CP16(bufb + 32768 + off, Wh + go);
            CP16(bufb + 32768 + NT * 128 + off, Wl + go);
        }
        CP_COMMIT();
    };

    load_chunk_async(0);
    CP_WAIT0();
    __syncthreads();

    float acc[4][4][4];
    #pragma unroll
    for (int i = 0; i < 4; i++)
        #pragma unroll
        for (int j = 0; j < 4; j++)
            #pragma unroll
            for (int q = 0; q < 4; q++) acc[i][j][q] = 0.f;

    const uint32_t khb = (lane >> 4) * 16;    // ldmatrix k-half (bytes)

    for (int c = 0; c < 4; c++) {
        if (c < 3) load_chunk_async(c + 1);   // overlaps with mma below
        const uint32_t bufb = sbase + (c & 1) * BUFB;
        #pragma unroll
        for (int ks = 0; ks < 4; ks++) {
            const uint32_t kb = ks * 32 + khb;
            uint32_t bh[2][4], bl[2][4];
            #pragma unroll
            for (int np = 0; np < 2; np++) {
                const int nr = wn * 32 + np * 16 + (lane & 15);
                const uint32_t off = nr * 128 + (kb ^ ((nr & 7) << 4));
                ldsm_x4(bh[np], bufb + 32768 + off);
                ldsm_x4(bl[np], bufb + 32768 + NT * 128 + off);
            }
            #pragma unroll
            for (int mt = 0; mt < 4; mt++) {
                const int mr = wm * 64 + mt * 16 + (lane & 15);
                const uint32_t off = mr * 128 + (kb ^ ((mr & 7) << 4));
                uint32_t ahf[4], alf[4];
                ldsm_x4(ahf, bufb + off);
                ldsm_x4(alf, bufb + 16384 + off);
                #pragma unroll
                for (int nt = 0; nt < 4; nt++) {
                    const int np = nt >> 1, hf = nt & 1;
                    mma16816(acc[mt][nt], ahf, bh[np][hf], bh[np][2 + hf]);
                    mma16816(acc[mt][nt], alf, bh[np][hf], bh[np][2 + hf]);
                    mma16816(acc[mt][nt], ahf, bl[np][hf], bl[np][2 + hf]);
                }
            }
        }
        if (c < 3) {
            CP_WAIT0();
            __syncthreads();
        }
    }
    __syncthreads();

    // ---- epilogue: frags -> smem stage -> (+bias) coalesced global store ----
    constexpr int NTP = NT + 4;
    float* stage = (float*)smc;
    #pragma unroll
    for (int mt = 0; mt < 4; mt++) {
        const int r = wm * 64 + mt * 16 + (lane >> 2);
        #pragma unroll
        for (int nt = 0; nt < 4; nt++) {
            const int cl = wn * 32 + nt * 8 + (lane & 3) * 2;
            stage[r * NTP + cl]           = acc[mt][nt][0];
            stage[r * NTP + cl + 1]       = acc[mt][nt][1];
            stage[(r + 8) * NTP + cl]     = acc[mt][nt][2];
            stage[(r + 8) * NTP + cl + 1] = acc[mt][nt][3];
        }
    }
    __syncthreads();

    for (int idx = tid; idx < 128 * (NT / 4); idx += NTH) {
        const int t = idx / (NT / 4);
        const int n = (idx % (NT / 4)) * 4;
        float4 v = *(const float4*)(stage + t * NTP + n);
        const float4 bb4 = (DST == 1 && n >= 128)
            ? *(const float4*)(bias2 + (n - 128))
            : *(const float4*)(bias1 + n);
        v.x += bb4.x; v.y += bb4.y; v.z += bb4.z; v.w += bb4.w;
        if (DST == 3) {
            const int h = n >> 5, d = n & 31;
            *(float4*)(g_vp + ((size_t)((b * NHD + h) * HWSZ) + yx0 + t) * HDC + d) = v;
        } else if (DST == 1) {
            if (n < 128) *(float4*)(g_loc + (size_t)(m0 + t) * 128 + n) = v;
            else         *(float4*)(g_att + (size_t)(m0 + t) * 64 + (n - 128)) = v;
        } else {
            *(float4*)(Cout + (size_t)(m0 + t) * 256 + n) = v;
        }
    }
}

// ---------------------------------------------------------------------------
// Sampling, phase-split:
//  P1: thread = (token,head) pair: local softmax + per-point corner weights
//      (zero-masked) + clamped packed coords -> smem
//  P2: warp gathers with float4 channel-lanes, writes bf16 hi/lo planes
// Block: 32 tokens, 256 threads. dyn smem: swgt4(32K) smout(32K) spak(8K)
// ---------------------------------------------------------------------------
__global__ __launch_bounds__(256)
void sampling_kernel()
{
    extern __shared__ float sms[];
    float4*   swgt4 = (float4*)sms;                    // [8*256]
    float*    smout = sms + 4 * 8 * 256;               // [32][256]
    uint32_t* spak  = (uint32_t*)(smout + 32 * 256);   // [8*256]

    const int tid  = threadIdx.x;
    const int g0   = blockIdx.x * 32;
    const int b    = g0 >> 12;
    const int w    = tid >> 5;
    const int lane = tid & 31;

    // ---- Phase 1: pair = tid (t = tid>>3, h = tid&7) ----
    {
        const int t = tid >> 3, h = tid & 7;
        // local softmax over the 8 points
        float e[NPP];
        const float4 a0 = *(const float4*)(g_att + (size_t)(g0 + t) * 64 + h * 8);
        const float4 a1 = *(const float4*)(g_att + (size_t)(g0 + t) * 64 + h * 8 + 4);
        e[0] = a0.x; e[1] = a0.y; e[2] = a0.z; e[3] = a0.w;
        e[4] = a1.x; e[5] = a1.y; e[6] = a1.z; e[7] = a1.w;
        float m = -1e30f;
        #pragma unroll
        for (int p = 0; p < NPP; p++) m = fmaxf(m, e[p]);
        float s = 0.f;
        #pragma unroll
        for (int p = 0; p < NPP; p++) { e[p] = expf(e[p] - m); s += e[p]; }
        const float inv = 1.f / s;

        float L[16];
        #pragma unroll
        for (int q = 0; q < 4; q++)
            *(float4*)(L + q * 4) = *(const float4*)(g_loc + (size_t)(g0 + t) * 128 + h * 16 + q * 4);

        #pragma unroll
        for (int p = 0; p < NPP; p++) {
            const float aw = e[p] * inv;
            const float x = L[2 * p] * (float)WW - 0.5f;
            const float y = L[2 * p + 1] * (float)HH - 0.5f;
            const float xf = floorf(x), yf = floorf(y);
            const float wx = x - xf, wy = y - yf;
            const int x0 = (int)xf, y0 = (int)yf;
            const int x1 = x0 + 1,  y1 = y0 + 1;
            const int x0c = min(max(x0, 0), WW - 1), x1c = min(max(x1, 0), WW - 1);
            const int y0c = min(max(y0, 0), HH - 1), y1c = min(max(y1, 0), HH - 1);
            const bool vx0 = (x0 >= 0) & (x0 < WW);
            const bool vx1 = (x1 >= 0) & (x1 < WW);
            const bool vy0 = (y0 >= 0) & (y0 < HH);
            const bool vy1 = (y1 >= 0) & (y1 < HH);
            float wa = aw * (1.f - wx) * (1.f - wy);
            float wb = aw * wx * (1.f - wy);
            float wc = aw * (1.f - wx) * wy;
            float wd = aw * wx * wy;
            wa = (vx0 && vy0) ? wa : 0.f;
            wb = (vx1 && vy0) ? wb : 0.f;
            wc = (vx0 && vy1) ? wc : 0.f;
            wd = (vx1 && vy1) ? wd : 0.f;
            swgt4[p * 256 + tid] = make_float4(wa, wb, wc, wd);
            spak[p * 256 + tid] = (uint32_t)x0c | ((uint32_t)x1c << 8) |
                                  ((uint32_t)y0c << 16) | ((uint32_t)y1c << 24);
        }
    }
    __syncthreads();

    // ---- Phase 2: gather. warp = 4 pairs x 8 channel-lanes ----
    const int sub = lane >> 3;
    const int d4  = (lane & 7) * 4;

    for (int i = 0; i < 8; i++) {
        const int pid = w * 32 + i * 4 + sub;   // pair id: t = pid>>3, h = pid&7
        const int tt  = pid >> 3;
        const int h   = pid & 7;
        const float* vpb = g_vp + (size_t)((b * NHD + h) * HWSZ) * HDC + d4;
        float4 acc = make_float4(0.f, 0.f, 0.f, 0.f);
        #pragma unroll
        for (int p = 0; p < NPP; p++) {
            const float4 wv = swgt4[p * 256 + pid];
            const uint32_t pk = spak[p * 256 + pid];
            const int x0c = pk & 255, x1c = (pk >> 8) & 255;
            const int y0r = ((pk >> 16) & 255) << 6;
            const int y1r = (pk >> 24) << 6;
            const float4 v00 = *(const float4*)(vpb + ((y0r + x0c) << 5));
            const float4 v01 = *(const float4*)(vpb + ((y0r + x1c) << 5));
            const float4 v10 = *(const float4*)(vpb + ((y1r + x0c) << 5));
            const float4 v11 = *(const float4*)(vpb + ((y1r + x1c) << 5));
            acc.x += wv.x * v00.x + wv.y * v01.x + wv.z * v10.x + wv.w * v11.x;
            acc.y += wv.x * v00.y + wv.y * v01.y + wv.z * v10.y + wv.w * v11.y;
            acc.z += wv.x * v00.z + wv.y * v01.z + wv.z * v10.z + wv.w * v11.z;
            acc.w += wv.x * v00.w + wv.y * v01.w + wv.z * v10.w + wv.w * v11.w;
        }
        *(float4*)(smout + tt * 256 + h * 32 + d4) = acc;
    }
    __syncthreads();

    // convert + coalesced token-major write of bf16 hi/lo planes
    for (int idx = tid; idx < 32 * 32; idx += 256) {
        const int t = idx >> 5, k8 = (idx & 31) * 8;
        const float4 v0 = *(const float4*)(smout + t * 256 + k8);
        const float4 v1 = *(const float4*)(smout + t * 256 + k8 + 4);
        uint2 h0, l0, h1, l1;
        pack_hilo4(v0, h0, l0); pack_hilo4(v1, h1, l1);
        *(uint4*)(g_mh + (size_t)(g0 + t) * DIMC + k8) = make_uint4(h0.x, h0.y, h1.x, h1.y);
        *(uint4*)(g_ml + (size_t)(g0 + t) * DIMC + k8) = make_uint4(l0.x, l0.y, l1.x, l1.y);
    }
}

// ---------------------------------------------------------------------------
extern "C" void kernel_launch(void* const* d_in, const int* in_sizes, int n_in,
                              void* d_out, int out_size) {
    const float* query = (const float*)d_in[0];
    const float* value = (const float*)d_in[1];
    const float* Wloc  = (const float*)d_in[2];
    const float* bloc  = (const float*)d_in[3];
    const float* Watt  = (const float*)d_in[4];
    const float* batt  = (const float*)d_in[5];
    const float* Wval  = (const float*)d_in[6];
    const float* bval  = (const float*)d_in[7];
    const float* Wout  = (const float*)d_in[8];
    const float* bout  = (const float*)d_in[9];
    float* out = (float*)d_out;

    const int sm192 = 2 * (32768 + 2 * 192 * 128) + 1024;   // ~161 KB
    const int sm256 = 2 * (32768 + 2 * 256 * 128) + 1024;   // ~197 KB
    const int smsamp = (4 * 8 * 256 + 32 * 256) * 4 + 8 * 256 * 4;   // 73728 B
    cudaFuncSetAttribute(tc_gemm<1, 192>, cudaFuncAttributeMaxDynamicSharedMemorySize, sm192);
    cudaFuncSetAttribute(tc_gemm<3, 256>, cudaFuncAttributeMaxDynamicSharedMemorySize, sm256);
    cudaFuncSetAttribute(tc_gemm<0, 256>, cudaFuncAttributeMaxDynamicSharedMemorySize, sm256);
    cudaFuncSetAttribute(sampling_kernel, cudaFuncAttributeMaxDynamicSharedMemorySize, smsamp);

    const int MBLK = NG / 128;   // 128 CTAs

    convert_act<<<1024, 256>>>(query, value);
    convert_w<<<88, 256>>>(Wloc, Watt, Wval, Wout);
    tc_gemm<1, 192><<<MBLK, 384, sm192>>>(bloc, batt, nullptr);
    tc_gemm<3, 256><<<MBLK, 512, sm256>>>(bval, nullptr, nullptr);
    sampling_kernel<<<NG / 32, 256, smsamp>>>();
    tc_gemm<0, 256><<<MBLK, 512, sm256>>>(bout, nullptr, out);
}